// round 15
// baseline (speedup 1.0000x reference)
#include <cuda_runtime.h>
#include <cuda_bf16.h>
#include <cuda_fp16.h>
#include <cstdint>
#include <math.h>

#define NROWS 4096
#define D     512
#define KCB   8192

// ---------------- scratch (device globals; no allocation) ----------------
__device__ float  g_L[(size_t)NROWS * KCB];     // logits
__device__ float  g_G[(size_t)NROWS * KCB];     // 2*gumbel noise (fp32)
__device__ __half g_E1[(size_t)NROWS * KCB];    // encodings (fp16)
__device__ __half g_A1[(size_t)NROWS * D];      // z fp16 2-way split
__device__ __half g_A2[(size_t)NROWS * D];
__device__ __half g_B1[(size_t)KCB * D];        // cb fp16 2-way split
__device__ __half g_B2[(size_t)KCB * D];
__device__ __half g_CT[(size_t)D * KCB];        // codebook^T (fp16)
__device__ float  g_c2[KCB];
__device__ float  g_z2[NROWS];
__device__ float  g_lse_p[NROWS];
__device__ float  g_lse_e[NROWS];
__device__ float  g_rowkld[NROWS];
__device__ float  g_avg_partial[32][KCB];
__device__ double g_sq_partial[128];

// ---------------- helpers ----------------
__device__ __forceinline__ uint32_t smem_u32(const void* p) {
    uint32_t a;
    asm("{ .reg .u64 t; cvta.to.shared.u64 t, %1; cvt.u32.u64 %0, t; }"
        : "=r"(a) : "l"(p));
    return a;
}
__device__ __forceinline__ void ldsm4(uint32_t* r, uint32_t a) {
    asm volatile("ldmatrix.sync.aligned.m8n8.x4.shared.b16 {%0,%1,%2,%3}, [%4];"
                 : "=r"(r[0]), "=r"(r[1]), "=r"(r[2]), "=r"(r[3]) : "r"(a));
}
__device__ __forceinline__ void mma_f16(float* d, const uint32_t* a, const uint32_t* b) {
    asm volatile("mma.sync.aligned.m16n8k16.row.col.f32.f16.f16.f32 "
                 "{%0,%1,%2,%3}, {%4,%5,%6,%7}, {%8,%9}, {%0,%1,%2,%3};"
                 : "+f"(d[0]), "+f"(d[1]), "+f"(d[2]), "+f"(d[3])
                 : "r"(a[0]), "r"(a[1]), "r"(a[2]), "r"(a[3]), "r"(b[0]), "r"(b[1]));
}
__device__ __forceinline__ void cp16(uint32_t dst, const void* src) {
    asm volatile("cp.async.cg.shared.global [%0], [%1], 16;" :: "r"(dst), "l"(src));
}
#define CP_COMMIT() asm volatile("cp.async.commit_group;")
#define CP_WAIT0()  asm volatile("cp.async.wait_group 0;")

// ---------------- threefry2x32, key = (0, 42), partitionable ----------------
__device__ __forceinline__ void threefry42(uint32_t x0, uint32_t x1,
                                           uint32_t& o0, uint32_t& o1) {
    const uint32_t ks0 = 0u, ks1 = 42u, ks2 = 0x1BD11BDAu ^ 0u ^ 42u;
#define TF_RND(r) { x0 += x1; x1 = __funnelshift_l(x1, x1, (r)); x1 ^= x0; }
    x0 += ks0; x1 += ks1;
    TF_RND(13) TF_RND(15) TF_RND(26) TF_RND(6)
    x0 += ks1; x1 += ks2 + 1u;
    TF_RND(17) TF_RND(29) TF_RND(16) TF_RND(24)
    x0 += ks2; x1 += ks0 + 2u;
    TF_RND(13) TF_RND(15) TF_RND(26) TF_RND(6)
    x0 += ks0; x1 += ks1 + 3u;
    TF_RND(17) TF_RND(29) TF_RND(16) TF_RND(24)
    x0 += ks1; x1 += ks2 + 4u;
    TF_RND(13) TF_RND(15) TF_RND(26) TF_RND(6)
    x0 += ks2; x1 += ks0 + 5u;
#undef TF_RND
    o0 = x0; o1 = x1;
}
__device__ __forceinline__ float bits_to_uniform(uint32_t b) {
    float f = __uint_as_float((b >> 9) | 0x3f800000u) - 1.0f;
    return fmaxf(0.0f, f);
}
__device__ __forceinline__ float gumbel2_from_idx(uint32_t idx) {
    uint32_t o0, o1;
    threefry42(0u, idx, o0, o1);
    float u = bits_to_uniform(o0 ^ o1);
    return -2.f * __logf(-__logf(u + 1e-10f) + 1e-10f);
}
__device__ __forceinline__ void comb(float& m, float& s1, float& s2,
                                     float m2, float s12, float s22) {
    float M = fmaxf(m, m2);
    float a = __expf(m - M), b = __expf(m2 - M);
    s1 = s1 * a + s12 * b;
    s2 = s2 * a + s22 * b;
    m = M;
}

// ---------------- split (one-time, fp16 2-way) + norms ----------------
__global__ void split_kernel(const float* __restrict__ z, const float* __restrict__ cb) {
    int row = blockIdx.x;
    const float* src;
    __half *d1, *d2;
    float* nrm;
    if (row < KCB) {
        src = cb + (size_t)row * D;
        d1 = g_B1 + (size_t)row * D; d2 = g_B2 + (size_t)row * D;
        nrm = g_c2 + row;
    } else {
        int r = row - KCB;
        src = z + (size_t)r * D;
        d1 = g_A1 + (size_t)r * D; d2 = g_A2 + (size_t)r * D;
        nrm = g_z2 + r;
    }
    float s = 0.f;
    for (int i = threadIdx.x; i < D; i += 128) {
        float v = src[i];
        s = fmaf(v, v, s);
        __half h1 = __float2half_rn(v);
        float r1 = v - __half2float(h1);
        d1[i] = h1; d2[i] = __float2half_rn(r1);
    }
    for (int o = 16; o; o >>= 1) s += __shfl_xor_sync(~0u, s, o);
    __shared__ float sm[4];
    if ((threadIdx.x & 31) == 0) sm[threadIdx.x >> 5] = s;
    __syncthreads();
    if (threadIdx.x == 0) *nrm = sm[0] + sm[1] + sm[2] + sm[3];
}

// ---------------- transpose codebook to fp16: CT[j][k] = cb[k][j] ----------------
__global__ __launch_bounds__(256) void transpose_kernel(const float* __restrict__ cb) {
    __shared__ float t[32][33];
    int k0 = blockIdx.x * 32, j0 = blockIdx.y * 32;
    int tx = threadIdx.x & 31, ty = threadIdx.x >> 5;
#pragma unroll
    for (int i = 0; i < 4; i++)
        t[ty + i * 8][tx] = cb[(size_t)(k0 + ty + i * 8) * D + j0 + tx];
    __syncthreads();
#pragma unroll
    for (int i = 0; i < 4; i++) {
        float v = t[tx][ty + i * 8];
        g_CT[(size_t)(j0 + ty + i * 8) * KCB + k0 + tx] = __float2half_rn(v);
    }
}

// ================ GEMM1 (fp16 HMMA, 3 products) + fused Gumbel ================
// The block's 128x128 logit tile needs exactly 16384 gumbel values; each of the
// 16 k-chunks computes 1024 of them (4/thread) on the otherwise-idle ALU pipes.
#define TS1 40
#define T1B (128 * TS1 * 2)          // 10240 B per tile
#define G1_STAGE_B (4 * T1B)         // 40960
#define G1_SMEM (2 * G1_STAGE_B)     // 81920

__global__ void __launch_bounds__(256, 2) gemm1_mma(const float* __restrict__ varq) {
    extern __shared__ __half smp[];
    uint32_t sb = smem_u32(smp);
    int tid = threadIdx.x, lane = tid & 31, wid = tid >> 5;
    int wm = (wid & 3) * 32, wn = (wid >> 2) * 64;
    int n0 = blockIdx.x * 128, m0 = blockIdx.y * 128;

    float acc[2][8][4];
#pragma unroll
    for (int i = 0; i < 2; i++)
#pragma unroll
        for (int j = 0; j < 8; j++)
#pragma unroll
            for (int q = 0; q < 4; q++) acc[i][j][q] = 0.f;

    int srow = tid >> 1, scol = (tid & 1) * 16;
    size_t aoff = (size_t)(m0 + srow) * D + scol;
    size_t boff = (size_t)(n0 + srow) * D + scol;
    uint32_t st_byte = (uint32_t)(srow * TS1 + scol) * 2;

    uint32_t a_off = (uint32_t)(((wm + (lane & 15)) * TS1 + (lane >> 4) * 8) * 2);
    uint32_t b_off = (uint32_t)(((wn + (lane >> 4) * 8 + (lane & 7)) * TS1 +
                                 ((lane >> 3) & 1) * 8) * 2);

#define G1_CPLOAD(s, kc)                                              \
    {                                                                 \
        uint32_t d0 = sb + (s) * G1_STAGE_B + st_byte;                \
        cp16(d0 + 0 * T1B,      g_A1 + aoff + (kc));                  \
        cp16(d0 + 0 * T1B + 16, g_A1 + aoff + (kc) + 8);              \
        cp16(d0 + 1 * T1B,      g_A2 + aoff + (kc));                  \
        cp16(d0 + 1 * T1B + 16, g_A2 + aoff + (kc) + 8);              \
        cp16(d0 + 2 * T1B,      g_B1 + boff + (kc));                  \
        cp16(d0 + 2 * T1B + 16, g_B1 + boff + (kc) + 8);              \
        cp16(d0 + 3 * T1B,      g_B2 + boff + (kc));                  \
        cp16(d0 + 3 * T1B + 16, g_B2 + boff + (kc) + 8);              \
    }

    G1_CPLOAD(0, 0);
    CP_COMMIT();
    int s = 0;
    for (int kc = 0; kc < D; kc += 32, s ^= 1) {
        CP_WAIT0();
        __syncthreads();
        if (kc + 32 < D) {
            G1_CPLOAD(s ^ 1, kc + 32);
            CP_COMMIT();
        }
        uint32_t stb = sb + s * G1_STAGE_B;

#pragma unroll
        for (int ks = 0; ks < 2; ks++) {
            uint32_t koff = (uint32_t)(ks * 16 * 2);
            uint32_t a[2][2][4];
#pragma unroll
            for (int v = 0; v < 2; v++)
#pragma unroll
                for (int mt = 0; mt < 2; mt++)
                    ldsm4(a[v][mt], stb + v * T1B + a_off + mt * 16 * TS1 * 2 + koff);
            uint32_t b[2][8][2];
#pragma unroll
            for (int v = 0; v < 2; v++)
#pragma unroll
                for (int np = 0; np < 4; np++) {
                    uint32_t r[4];
                    ldsm4(r, stb + (2 + v) * T1B + b_off + np * 16 * TS1 * 2 + koff);
                    b[v][2 * np][0] = r[0]; b[v][2 * np][1] = r[1];
                    b[v][2 * np + 1][0] = r[2]; b[v][2 * np + 1][1] = r[3];
                }
            const int pa[3] = {0, 0, 1};
            const int pb[3] = {0, 1, 0};
#pragma unroll
            for (int p = 0; p < 3; p++)
#pragma unroll
                for (int mt = 0; mt < 2; mt++)
#pragma unroll
                    for (int nt = 0; nt < 8; nt++)
                        mma_f16(acc[mt][nt], a[pa[p]][mt], b[pb[p]][nt]);
        }

        // fused gumbel: 1024 of the tile's 16384 values per chunk (ALU fills
        // tensor-pipe bubbles via warp interleaving)
        {
            int e = (kc >> 5) * 1024 + tid * 4;      // tile-local element
            int r = e >> 7, c = e & 127;
            uint32_t idx = (uint32_t)((m0 + r) * KCB + n0 + c);
            float4 gv;
            gv.x = gumbel2_from_idx(idx);
            gv.y = gumbel2_from_idx(idx + 1);
            gv.z = gumbel2_from_idx(idx + 2);
            gv.w = gumbel2_from_idx(idx + 3);
            *(float4*)(g_G + (size_t)(m0 + r) * KCB + n0 + c) = gv;
        }
    }

    float w = 0.5f / fmaxf(varq[0], 1e-10f);
#pragma unroll
    for (int mt = 0; mt < 2; mt++) {
        int r = m0 + wm + mt * 16 + (lane >> 2);
        float z0 = g_z2[r], z1 = g_z2[r + 8];
#pragma unroll
        for (int nt = 0; nt < 8; nt++) {
            int c = n0 + wn + nt * 8 + (lane & 3) * 2;
            float c20 = g_c2[c], c21 = g_c2[c + 1];
            float2 u0, u1;
            u0.x = 2.f * w * acc[mt][nt][0] - w * (z0 + c20);
            u0.y = 2.f * w * acc[mt][nt][1] - w * (z0 + c21);
            u1.x = 2.f * w * acc[mt][nt][2] - w * (z1 + c20);
            u1.y = 2.f * w * acc[mt][nt][3] - w * (z1 + c21);
            *(float2*)(g_L + (size_t)r * KCB + c) = u0;
            *(float2*)(g_L + (size_t)(r + 8) * KCB + c) = u1;
        }
    }
}

// ---------------- pass C: row softmax stats; reads fused gumbel ----------------
__global__ __launch_bounds__(512) void passC_kernel() {
    int n = blockIdx.x;
    size_t base = (size_t)n * KCB;
    int tid = threadIdx.x;

    __shared__ float s_ev[KCB];
    float mp = -3.4e38f, s1 = 0.f, s2 = 0.f;
    float me = -3.4e38f, se = 0.f;

#pragma unroll 4
    for (int it = 0; it < 16; it++) {
        int k = tid + it * 512;
        float l = g_L[base + k];
        float gg = g_G[base + k];
        float e = fmaf(2.f, l, gg);
        s_ev[k] = e;
        if (l <= mp) {
            float b = __expf(l - mp);
            s1 += b; s2 = fmaf(l, b, s2);
        } else {
            float a = __expf(mp - l);
            s1 = fmaf(s1, a, 1.f);
            s2 = fmaf(s2, a, l);
            mp = l;
        }
        if (e <= me) {
            se += __expf(e - me);
        } else {
            se = fmaf(se, __expf(me - e), 1.f);
            me = e;
        }
    }

    for (int o = 16; o; o >>= 1) {
        float m2, a2, b2;
        m2 = __shfl_xor_sync(~0u, mp, o); a2 = __shfl_xor_sync(~0u, s1, o); b2 = __shfl_xor_sync(~0u, s2, o);
        comb(mp, s1, s2, m2, a2, b2);
        float d0 = 0.f;
        m2 = __shfl_xor_sync(~0u, me, o); a2 = __shfl_xor_sync(~0u, se, o); b2 = __shfl_xor_sync(~0u, d0, o);
        comb(me, se, d0, m2, a2, b2);
    }

    __shared__ float sm[16][5];
    __shared__ float s_lse;
    if ((tid & 31) == 0) {
        int w = tid >> 5;
        sm[w][0] = mp; sm[w][1] = s1; sm[w][2] = s2;
        sm[w][3] = me; sm[w][4] = se;
    }
    __syncthreads();
    if (tid == 0) {
        float Mp = sm[0][0], S1 = sm[0][1], S2 = sm[0][2];
        float Me = sm[0][3], Se = sm[0][4];
        for (int w = 1; w < 16; w++) {
            comb(Mp, S1, S2, sm[w][0], sm[w][1], sm[w][2]);
            float d = 0.f;
            comb(Me, Se, d, sm[w][3], sm[w][4], 0.f);
        }
        float lsep = Mp + logf(S1);
        g_lse_p[n]  = lsep;
        g_rowkld[n] = S2 / S1 - lsep;
        float lsee = Me + logf(Se);
        g_lse_e[n]  = lsee;
        s_lse = lsee;
    }
    __syncthreads();
    float lse = s_lse;
#pragma unroll 4
    for (int it = 0; it < 8; it++) {
        int k = tid * 2 + it * 1024;
        float p0 = __expf(s_ev[k] - lse);
        float p1 = __expf(s_ev[k + 1] - lse);
        __half2 h2 = __floats2half2_rn(p0, p1);
        *(__half2*)(g_E1 + base + k) = h2;
    }
}

// ---------------- avg_probs partials (column pass over L) ----------------
__global__ __launch_bounds__(256) void avg_kernel() {
    int k = blockIdx.x * 256 + threadIdx.x;
    int c = blockIdx.y;
    const float* base = g_L + (size_t)c * 128 * KCB + k;
    const float* lse  = g_lse_p + c * 128;
    float s = 0.f;
#pragma unroll 4
    for (int n = 0; n < 128; n++)
        s += __expf(base[(size_t)n * KCB] - lse[n]);
    g_avg_partial[c][k] = s;
}

// ================ GEMM2 (fp16 HMMA, 1 product, k-chunk 32, 1 sync/iter) ================
#define TS2 40
#define T2B (128 * TS2 * 2)          // 10240 B per tile
#define G2_STAGE_B (2 * T2B)         // 20480 (E1, CT)
#define G2_SMEM (2 * G2_STAGE_B)     // 40960

__global__ __launch_bounds__(256) void gemm2_mma(const float* __restrict__ Z,
                                                 float* __restrict__ out) {
    extern __shared__ __half smp2[];
    uint32_t sb = smem_u32(smp2);
    int tid = threadIdx.x, lane = tid & 31, wid = tid >> 5;
    int wm = (wid & 3) * 32, wn = (wid >> 2) * 64;
    int j0 = blockIdx.x * 128, m0 = blockIdx.y * 128;

    float acc[2][8][4];
#pragma unroll
    for (int i = 0; i < 2; i++)
#pragma unroll
        for (int j = 0; j < 8; j++)
#pragma unroll
            for (int q = 0; q < 4; q++) acc[i][j][q] = 0.f;

    int srow = tid >> 1, scol = (tid & 1) * 16;
    size_t aoff = (size_t)(m0 + srow) * KCB + scol;
    size_t boff = (size_t)(j0 + srow) * KCB + scol;
    uint32_t st_byte = (uint32_t)(srow * TS2 + scol) * 2;

    uint32_t a_off = (uint32_t)(((wm + (lane & 15)) * TS2 + (lane >> 4) * 8) * 2);
    uint32_t b_off = (uint32_t)(((wn + (lane >> 4) * 8 + (lane & 7)) * TS2 +
                                 ((lane >> 3) & 1) * 8) * 2);

#define G2_CPLOAD(s, kc)                                              \
    {                                                                 \
        uint32_t d0 = sb + (s) * G2_STAGE_B + st_byte;                \
        cp16(d0 + 0 * T2B,      g_E1 + aoff + (kc));                  \
        cp16(d0 + 0 * T2B + 16, g_E1 + aoff + (kc) + 8);              \
        cp16(d0 + 1 * T2B,      g_CT + boff + (kc));                  \
        cp16(d0 + 1 * T2B + 16, g_CT + boff + (kc) + 8);              \
    }

    G2_CPLOAD(0, 0);
    CP_COMMIT();
    int s = 0;
    for (int kc = 0; kc < KCB; kc += 32, s ^= 1) {
        CP_WAIT0();
        __syncthreads();
        if (kc + 32 < KCB) {
            G2_CPLOAD(s ^ 1, kc + 32);
            CP_COMMIT();
        }
        uint32_t stb = sb + s * G2_STAGE_B;

#pragma unroll
        for (int ks = 0; ks < 2; ks++) {
            uint32_t koff = (uint32_t)(ks * 16 * 2);
            uint32_t a[2][4];
#pragma unroll
            for (int mt = 0; mt < 2; mt++)
                ldsm4(a[mt], stb + a_off + mt * 16 * TS2 * 2 + koff);
            uint32_t b[8][2];
#pragma unroll
            for (int np = 0; np < 4; np++) {
                uint32_t r[4];
                ldsm4(r, stb + T2B + b_off + np * 16 * TS2 * 2 + koff);
                b[2 * np][0] = r[0]; b[2 * np][1] = r[1];
                b[2 * np + 1][0] = r[2]; b[2 * np + 1][1] = r[3];
            }
#pragma unroll
            for (int mt = 0; mt < 2; mt++)
#pragma unroll
                for (int nt = 0; nt < 8; nt++)
                    mma_f16(acc[mt][nt], a[mt], b[nt]);
        }
    }

    float sq = 0.f;
#pragma unroll
    for (int mt = 0; mt < 2; mt++) {
        int r = m0 + wm + mt * 16 + (lane >> 2);
#pragma unroll
        for (int nt = 0; nt < 8; nt++) {
            int c = j0 + wn + nt * 8 + (lane & 3) * 2;
            size_t o0 = (size_t)r * D + c;
            size_t o1 = (size_t)(r + 8) * D + c;
            float2 u0, u1;
            u0.x = acc[mt][nt][0]; u0.y = acc[mt][nt][1];
            u1.x = acc[mt][nt][2]; u1.y = acc[mt][nt][3];
            *(float2*)(out + o0) = u0;
            *(float2*)(out + o1) = u1;
            float d;
            d = Z[o0] - u0.x;     sq = fmaf(d, d, sq);
            d = Z[o0 + 1] - u0.y; sq = fmaf(d, d, sq);
            d = Z[o1] - u1.x;     sq = fmaf(d, d, sq);
            d = Z[o1 + 1] - u1.y; sq = fmaf(d, d, sq);
        }
    }
    for (int o = 16; o; o >>= 1) sq += __shfl_xor_sync(~0u, sq, o);
    __shared__ float ssq[8];
    if ((tid & 31) == 0) ssq[tid >> 5] = sq;
    __syncthreads();
    if (tid == 0) {
        float t = 0.f;
#pragma unroll
        for (int i = 0; i < 8; i++) t += ssq[i];
        g_sq_partial[blockIdx.y * gridDim.x + blockIdx.x] = (double)t;
    }
}

// ---------------- finalize: loss + perplexity ----------------
__global__ __launch_bounds__(256) void finalize_kernel(const float* __restrict__ varq,
                                                       float* __restrict__ out) {
    int tid = threadIdx.x;
    double ent = 0.0, kld = 0.0, sq = 0.0;
    for (int k = tid; k < KCB; k += 256) {
        float a = 0.f;
#pragma unroll
        for (int c = 0; c < 32; c++) a += g_avg_partial[c][k];
        a *= (1.0f / (float)NROWS);
        ent += (double)(a * logf(a + 1e-7f));
    }
    for (int r = tid; r < NROWS; r += 256) kld += (double)g_rowkld[r];
    if (tid < 128) sq = g_sq_partial[tid];
    __shared__ double red[3][256];
    red[0][tid] = ent; red[1][tid] = kld; red[2][tid] = sq;
    __syncthreads();
    for (int o = 128; o; o >>= 1) {
        if (tid < o) {
            red[0][tid] += red[0][tid + o];
            red[1][tid] += red[1][tid + o];
            red[2][tid] += red[2][tid + o];
        }
        __syncthreads();
    }
    if (tid == 0) {
        float w = 0.5f / fmaxf(varq[0], 1e-10f);
        double loss = red[1][0] / 8.0 + (double)w * red[2][0] / 8.0;
        out[(size_t)NROWS * D]     = (float)loss;
        out[(size_t)NROWS * D + 1] = expf(-(float)red[0][0]);
    }
}

// ---------------- launch ----------------
extern "C" void kernel_launch(void* const* d_in, const int* in_sizes, int n_in,
                              void* d_out, int out_size) {
    const float* z    = (const float*)d_in[0];
    const float* varq = (const float*)d_in[1];
    const float* cb   = (const float*)d_in[2];
    float* out = (float*)d_out;

    static cudaStream_t s2 = nullptr;
    static cudaEvent_t evC = nullptr, evD = nullptr;
    static int infra_ok = -1;
    if (infra_ok < 0) {
        infra_ok = 1;
        if (cudaStreamCreateWithFlags(&s2, cudaStreamNonBlocking) != cudaSuccess) infra_ok = 0;
        if (cudaEventCreateWithFlags(&evC, cudaEventDisableTiming) != cudaSuccess) infra_ok = 0;
        if (cudaEventCreateWithFlags(&evD, cudaEventDisableTiming) != cudaSuccess) infra_ok = 0;
    }
    cudaFuncSetAttribute(gemm1_mma, cudaFuncAttributeMaxDynamicSharedMemorySize, G1_SMEM);
    cudaFuncSetAttribute(gemm2_mma, cudaFuncAttributeMaxDynamicSharedMemorySize, G2_SMEM);

    split_kernel<<<KCB + NROWS, 128>>>(z, cb);
    transpose_kernel<<<dim3(KCB / 32, D / 32), 256>>>(cb);
    gemm1_mma<<<dim3(KCB / 128, NROWS / 128), 256, G1_SMEM>>>(varq);
    passC_kernel<<<NROWS, 512>>>();

    if (infra_ok) {
        cudaEventRecord(evC, 0);
        cudaStreamWaitEvent(s2, evC, 0);
        avg_kernel<<<dim3(32, 32), 256, 0, s2>>>();
        cudaEventRecord(evD, s2);

        gemm2_mma<<<dim3(D / 128, NROWS / 128), 256, G2_SMEM>>>(z, out);

        cudaStreamWaitEvent(0, evD, 0);
        finalize_kernel<<<1, 256>>>(varq, out);
    } else {
        avg_kernel<<<dim3(32, 32), 256>>>();
        gemm2_mma<<<dim3(D / 128, NROWS / 128), 256, G2_SMEM>>>(z, out);
        finalize_kernel<<<1, 256>>>(varq, out);
    }
}

// round 16
// speedup vs baseline: 1.0245x; 1.0245x over previous
#include <cuda_runtime.h>
#include <cuda_bf16.h>
#include <cuda_fp16.h>
#include <cstdint>
#include <math.h>

#define NROWS 4096
#define D     512
#define KCB   8192
#define GTOTAL ((size_t)NROWS * KCB)

// ---------------- scratch (device globals; no allocation) ----------------
__device__ float  g_L[(size_t)NROWS * KCB];     // logits
__device__ float  g_G[(size_t)NROWS * KCB];     // 2*gumbel noise (fp32)
__device__ __half g_E1[(size_t)NROWS * KCB];    // encodings (fp16)
__device__ __half g_A1[(size_t)NROWS * D];      // z fp16 2-way split
__device__ __half g_A2[(size_t)NROWS * D];
__device__ __half g_B1[(size_t)KCB * D];        // cb fp16 2-way split
__device__ __half g_B2[(size_t)KCB * D];
__device__ __half g_CT[(size_t)D * KCB];        // codebook^T (fp16)
__device__ float  g_c2[KCB];
__device__ float  g_z2[NROWS];
__device__ float  g_lse_p[NROWS];
__device__ float  g_lse_e[NROWS];
__device__ float  g_rowkld[NROWS];
__device__ float  g_avg_partial[32][KCB];
__device__ double g_sq_partial[128];

// ---------------- helpers ----------------
__device__ __forceinline__ uint32_t smem_u32(const void* p) {
    uint32_t a;
    asm("{ .reg .u64 t; cvta.to.shared.u64 t, %1; cvt.u32.u64 %0, t; }"
        : "=r"(a) : "l"(p));
    return a;
}
__device__ __forceinline__ void ldsm4(uint32_t* r, uint32_t a) {
    asm volatile("ldmatrix.sync.aligned.m8n8.x4.shared.b16 {%0,%1,%2,%3}, [%4];"
                 : "=r"(r[0]), "=r"(r[1]), "=r"(r[2]), "=r"(r[3]) : "r"(a));
}
__device__ __forceinline__ void mma_f16(float* d, const uint32_t* a, const uint32_t* b) {
    asm volatile("mma.sync.aligned.m16n8k16.row.col.f32.f16.f16.f32 "
                 "{%0,%1,%2,%3}, {%4,%5,%6,%7}, {%8,%9}, {%0,%1,%2,%3};"
                 : "+f"(d[0]), "+f"(d[1]), "+f"(d[2]), "+f"(d[3])
                 : "r"(a[0]), "r"(a[1]), "r"(a[2]), "r"(a[3]), "r"(b[0]), "r"(b[1]));
}
__device__ __forceinline__ void cp16(uint32_t dst, const void* src) {
    asm volatile("cp.async.cg.shared.global [%0], [%1], 16;" :: "r"(dst), "l"(src));
}
#define CP_COMMIT() asm volatile("cp.async.commit_group;")
#define CP_WAIT0()  asm volatile("cp.async.wait_group 0;")

// ---------------- threefry2x32, key = (0, 42), partitionable ----------------
__device__ __forceinline__ void threefry42(uint32_t x0, uint32_t x1,
                                           uint32_t& o0, uint32_t& o1) {
    const uint32_t ks0 = 0u, ks1 = 42u, ks2 = 0x1BD11BDAu ^ 0u ^ 42u;
#define TF_RND(r) { x0 += x1; x1 = __funnelshift_l(x1, x1, (r)); x1 ^= x0; }
    x0 += ks0; x1 += ks1;
    TF_RND(13) TF_RND(15) TF_RND(26) TF_RND(6)
    x0 += ks1; x1 += ks2 + 1u;
    TF_RND(17) TF_RND(29) TF_RND(16) TF_RND(24)
    x0 += ks2; x1 += ks0 + 2u;
    TF_RND(13) TF_RND(15) TF_RND(26) TF_RND(6)
    x0 += ks0; x1 += ks1 + 3u;
    TF_RND(17) TF_RND(29) TF_RND(16) TF_RND(24)
    x0 += ks1; x1 += ks2 + 4u;
    TF_RND(13) TF_RND(15) TF_RND(26) TF_RND(6)
    x0 += ks2; x1 += ks0 + 5u;
#undef TF_RND
    o0 = x0; o1 = x1;
}
__device__ __forceinline__ float bits_to_uniform(uint32_t b) {
    float f = __uint_as_float((b >> 9) | 0x3f800000u) - 1.0f;
    return fmaxf(0.0f, f);
}
__device__ __forceinline__ float gumbel2_from_idx(uint32_t idx) {
    uint32_t o0, o1;
    threefry42(0u, idx, o0, o1);
    float u = bits_to_uniform(o0 ^ o1);
    return -2.f * __logf(-__logf(u + 1e-10f) + 1e-10f);
}
__device__ __forceinline__ void comb(float& m, float& s1, float& s2,
                                     float m2, float s12, float s22) {
    float M = fmaxf(m, m2);
    float a = __expf(m - M), b = __expf(m2 - M);
    s1 = s1 * a + s12 * b;
    s2 = s2 * a + s22 * b;
    m = M;
}

// ---------------- split + norms + fused gumbel slice ----------------
// 12288 blocks; each also produces a contiguous 2731-element slice of g_G.
// The threefry ALU work overlaps this kernel's DRAM stalls.
#define GSLICE 2731

__global__ void split_kernel(const float* __restrict__ z, const float* __restrict__ cb) {
    int row = blockIdx.x;
    const float* src;
    __half *d1, *d2;
    float* nrm;
    if (row < KCB) {
        src = cb + (size_t)row * D;
        d1 = g_B1 + (size_t)row * D; d2 = g_B2 + (size_t)row * D;
        nrm = g_c2 + row;
    } else {
        int r = row - KCB;
        src = z + (size_t)r * D;
        d1 = g_A1 + (size_t)r * D; d2 = g_A2 + (size_t)r * D;
        nrm = g_z2 + r;
    }
    float s = 0.f;
    for (int i = threadIdx.x; i < D; i += 128) {
        float v = src[i];
        s = fmaf(v, v, s);
        __half h1 = __float2half_rn(v);
        float r1 = v - __half2float(h1);
        d1[i] = h1; d2[i] = __float2half_rn(r1);
    }
    // fused gumbel slice (coalesced within warp)
    {
        size_t start = (size_t)blockIdx.x * GSLICE;
        for (int i = threadIdx.x; i < GSLICE; i += 128) {
            size_t idx = start + (size_t)i;
            if (idx < GTOTAL)
                g_G[idx] = gumbel2_from_idx((uint32_t)idx);
        }
    }
    for (int o = 16; o; o >>= 1) s += __shfl_xor_sync(~0u, s, o);
    __shared__ float sm[4];
    if ((threadIdx.x & 31) == 0) sm[threadIdx.x >> 5] = s;
    __syncthreads();
    if (threadIdx.x == 0) *nrm = sm[0] + sm[1] + sm[2] + sm[3];
}

// ---------------- transpose codebook to fp16: CT[j][k] = cb[k][j] ----------------
__global__ __launch_bounds__(256) void transpose_kernel(const float* __restrict__ cb) {
    __shared__ float t[32][33];
    int k0 = blockIdx.x * 32, j0 = blockIdx.y * 32;
    int tx = threadIdx.x & 31, ty = threadIdx.x >> 5;
#pragma unroll
    for (int i = 0; i < 4; i++)
        t[ty + i * 8][tx] = cb[(size_t)(k0 + ty + i * 8) * D + j0 + tx];
    __syncthreads();
#pragma unroll
    for (int i = 0; i < 4; i++) {
        float v = t[tx][ty + i * 8];
        g_CT[(size_t)(j0 + ty + i * 8) * KCB + k0 + tx] = __float2half_rn(v);
    }
}

// ================ GEMM1 (fp16 HMMA, 3 products, k-chunk 32, 1 sync/iter) ================
#define TS1 40
#define T1B (128 * TS1 * 2)          // 10240 B per tile
#define G1_STAGE_B (4 * T1B)         // 40960
#define G1_SMEM (2 * G1_STAGE_B)     // 81920

__global__ __launch_bounds__(256) void gemm1_mma(const float* __restrict__ varq) {
    extern __shared__ __half smp[];
    uint32_t sb = smem_u32(smp);
    int tid = threadIdx.x, lane = tid & 31, wid = tid >> 5;
    int wm = (wid & 3) * 32, wn = (wid >> 2) * 64;
    int n0 = blockIdx.x * 128, m0 = blockIdx.y * 128;

    float acc[2][8][4];
#pragma unroll
    for (int i = 0; i < 2; i++)
#pragma unroll
        for (int j = 0; j < 8; j++)
#pragma unroll
            for (int q = 0; q < 4; q++) acc[i][j][q] = 0.f;

    int srow = tid >> 1, scol = (tid & 1) * 16;
    size_t aoff = (size_t)(m0 + srow) * D + scol;
    size_t boff = (size_t)(n0 + srow) * D + scol;
    uint32_t st_byte = (uint32_t)(srow * TS1 + scol) * 2;

    uint32_t a_off = (uint32_t)(((wm + (lane & 15)) * TS1 + (lane >> 4) * 8) * 2);
    uint32_t b_off = (uint32_t)(((wn + (lane >> 4) * 8 + (lane & 7)) * TS1 +
                                 ((lane >> 3) & 1) * 8) * 2);

#define G1_CPLOAD(s, kc)                                              \
    {                                                                 \
        uint32_t d0 = sb + (s) * G1_STAGE_B + st_byte;                \
        cp16(d0 + 0 * T1B,      g_A1 + aoff + (kc));                  \
        cp16(d0 + 0 * T1B + 16, g_A1 + aoff + (kc) + 8);              \
        cp16(d0 + 1 * T1B,      g_A2 + aoff + (kc));                  \
        cp16(d0 + 1 * T1B + 16, g_A2 + aoff + (kc) + 8);              \
        cp16(d0 + 2 * T1B,      g_B1 + boff + (kc));                  \
        cp16(d0 + 2 * T1B + 16, g_B1 + boff + (kc) + 8);              \
        cp16(d0 + 3 * T1B,      g_B2 + boff + (kc));                  \
        cp16(d0 + 3 * T1B + 16, g_B2 + boff + (kc) + 8);              \
    }

    G1_CPLOAD(0, 0);
    CP_COMMIT();
    int s = 0;
    for (int kc = 0; kc < D; kc += 32, s ^= 1) {
        CP_WAIT0();
        __syncthreads();
        if (kc + 32 < D) {
            G1_CPLOAD(s ^ 1, kc + 32);
            CP_COMMIT();
        }
        uint32_t stb = sb + s * G1_STAGE_B;

#pragma unroll
        for (int ks = 0; ks < 2; ks++) {
            uint32_t koff = (uint32_t)(ks * 16 * 2);
            uint32_t a[2][2][4];
#pragma unroll
            for (int v = 0; v < 2; v++)
#pragma unroll
                for (int mt = 0; mt < 2; mt++)
                    ldsm4(a[v][mt], stb + v * T1B + a_off + mt * 16 * TS1 * 2 + koff);
            uint32_t b[2][8][2];
#pragma unroll
            for (int v = 0; v < 2; v++)
#pragma unroll
                for (int np = 0; np < 4; np++) {
                    uint32_t r[4];
                    ldsm4(r, stb + (2 + v) * T1B + b_off + np * 16 * TS1 * 2 + koff);
                    b[v][2 * np][0] = r[0]; b[v][2 * np][1] = r[1];
                    b[v][2 * np + 1][0] = r[2]; b[v][2 * np + 1][1] = r[3];
                }
            const int pa[3] = {0, 0, 1};
            const int pb[3] = {0, 1, 0};
#pragma unroll
            for (int p = 0; p < 3; p++)
#pragma unroll
                for (int mt = 0; mt < 2; mt++)
#pragma unroll
                    for (int nt = 0; nt < 8; nt++)
                        mma_f16(acc[mt][nt], a[pa[p]][mt], b[pb[p]][nt]);
        }
    }

    float w = 0.5f / fmaxf(varq[0], 1e-10f);
#pragma unroll
    for (int mt = 0; mt < 2; mt++) {
        int r = m0 + wm + mt * 16 + (lane >> 2);
        float z0 = g_z2[r], z1 = g_z2[r + 8];
#pragma unroll
        for (int nt = 0; nt < 8; nt++) {
            int c = n0 + wn + nt * 8 + (lane & 3) * 2;
            float c20 = g_c2[c], c21 = g_c2[c + 1];
            float2 u0, u1;
            u0.x = 2.f * w * acc[mt][nt][0] - w * (z0 + c20);
            u0.y = 2.f * w * acc[mt][nt][1] - w * (z0 + c21);
            u1.x = 2.f * w * acc[mt][nt][2] - w * (z1 + c20);
            u1.y = 2.f * w * acc[mt][nt][3] - w * (z1 + c21);
            *(float2*)(g_L + (size_t)r * KCB + c) = u0;
            *(float2*)(g_L + (size_t)(r + 8) * KCB + c) = u1;
        }
    }
}

// ---------------- pass C: row softmax stats; reads precomputed gumbel ----------------
__global__ __launch_bounds__(512) void passC_kernel() {
    int n = blockIdx.x;
    size_t base = (size_t)n * KCB;
    int tid = threadIdx.x;

    __shared__ float s_ev[KCB];
    float mp = -3.4e38f, s1 = 0.f, s2 = 0.f;
    float me = -3.4e38f, se = 0.f;

#pragma unroll 4
    for (int it = 0; it < 16; it++) {
        int k = tid + it * 512;
        float l = g_L[base + k];
        float gg = g_G[base + k];
        float e = fmaf(2.f, l, gg);
        s_ev[k] = e;
        if (l <= mp) {
            float b = __expf(l - mp);
            s1 += b; s2 = fmaf(l, b, s2);
        } else {
            float a = __expf(mp - l);
            s1 = fmaf(s1, a, 1.f);
            s2 = fmaf(s2, a, l);
            mp = l;
        }
        if (e <= me) {
            se += __expf(e - me);
        } else {
            se = fmaf(se, __expf(me - e), 1.f);
            me = e;
        }
    }

    for (int o = 16; o; o >>= 1) {
        float m2, a2, b2;
        m2 = __shfl_xor_sync(~0u, mp, o); a2 = __shfl_xor_sync(~0u, s1, o); b2 = __shfl_xor_sync(~0u, s2, o);
        comb(mp, s1, s2, m2, a2, b2);
        float d0 = 0.f;
        m2 = __shfl_xor_sync(~0u, me, o); a2 = __shfl_xor_sync(~0u, se, o); b2 = __shfl_xor_sync(~0u, d0, o);
        comb(me, se, d0, m2, a2, b2);
    }

    __shared__ float sm[16][5];
    __shared__ float s_lse;
    if ((tid & 31) == 0) {
        int w = tid >> 5;
        sm[w][0] = mp; sm[w][1] = s1; sm[w][2] = s2;
        sm[w][3] = me; sm[w][4] = se;
    }
    __syncthreads();
    if (tid == 0) {
        float Mp = sm[0][0], S1 = sm[0][1], S2 = sm[0][2];
        float Me = sm[0][3], Se = sm[0][4];
        for (int w = 1; w < 16; w++) {
            comb(Mp, S1, S2, sm[w][0], sm[w][1], sm[w][2]);
            float d = 0.f;
            comb(Me, Se, d, sm[w][3], sm[w][4], 0.f);
        }
        float lsep = Mp + logf(S1);
        g_lse_p[n]  = lsep;
        g_rowkld[n] = S2 / S1 - lsep;
        float lsee = Me + logf(Se);
        g_lse_e[n]  = lsee;
        s_lse = lsee;
    }
    __syncthreads();
    float lse = s_lse;
#pragma unroll 4
    for (int it = 0; it < 8; it++) {
        int k = tid * 2 + it * 1024;
        float p0 = __expf(s_ev[k] - lse);
        float p1 = __expf(s_ev[k + 1] - lse);
        __half2 h2 = __floats2half2_rn(p0, p1);
        *(__half2*)(g_E1 + base + k) = h2;
    }
}

// ---------------- avg_probs partials (column pass over L) ----------------
__global__ __launch_bounds__(256) void avg_kernel() {
    int k = blockIdx.x * 256 + threadIdx.x;
    int c = blockIdx.y;
    const float* base = g_L + (size_t)c * 128 * KCB + k;
    const float* lse  = g_lse_p + c * 128;
    float s = 0.f;
#pragma unroll 4
    for (int n = 0; n < 128; n++)
        s += __expf(base[(size_t)n * KCB] - lse[n]);
    g_avg_partial[c][k] = s;
}

// ================ GEMM2 (fp16 HMMA, 1 product, k-chunk 32, 1 sync/iter) ================
#define TS2 40
#define T2B (128 * TS2 * 2)          // 10240 B per tile
#define G2_STAGE_B (2 * T2B)         // 20480 (E1, CT)
#define G2_SMEM (2 * G2_STAGE_B)     // 40960

__global__ __launch_bounds__(256) void gemm2_mma(const float* __restrict__ Z,
                                                 float* __restrict__ out) {
    extern __shared__ __half smp2[];
    uint32_t sb = smem_u32(smp2);
    int tid = threadIdx.x, lane = tid & 31, wid = tid >> 5;
    int wm = (wid & 3) * 32, wn = (wid >> 2) * 64;
    int j0 = blockIdx.x * 128, m0 = blockIdx.y * 128;

    float acc[2][8][4];
#pragma unroll
    for (int i = 0; i < 2; i++)
#pragma unroll
        for (int j = 0; j < 8; j++)
#pragma unroll
            for (int q = 0; q < 4; q++) acc[i][j][q] = 0.f;

    int srow = tid >> 1, scol = (tid & 1) * 16;
    size_t aoff = (size_t)(m0 + srow) * KCB + scol;
    size_t boff = (size_t)(j0 + srow) * KCB + scol;
    uint32_t st_byte = (uint32_t)(srow * TS2 + scol) * 2;

    uint32_t a_off = (uint32_t)(((wm + (lane & 15)) * TS2 + (lane >> 4) * 8) * 2);
    uint32_t b_off = (uint32_t)(((wn + (lane >> 4) * 8 + (lane & 7)) * TS2 +
                                 ((lane >> 3) & 1) * 8) * 2);

#define G2_CPLOAD(s, kc)                                              \
    {                                                                 \
        uint32_t d0 = sb + (s) * G2_STAGE_B + st_byte;                \
        cp16(d0 + 0 * T2B,      g_E1 + aoff + (kc));                  \
        cp16(d0 + 0 * T2B + 16, g_E1 + aoff + (kc) + 8);              \
        cp16(d0 + 1 * T2B,      g_CT + boff + (kc));                  \
        cp16(d0 + 1 * T2B + 16, g_CT + boff + (kc) + 8);              \
    }

    G2_CPLOAD(0, 0);
    CP_COMMIT();
    int s = 0;
    for (int kc = 0; kc < KCB; kc += 32, s ^= 1) {
        CP_WAIT0();
        __syncthreads();
        if (kc + 32 < KCB) {
            G2_CPLOAD(s ^ 1, kc + 32);
            CP_COMMIT();
        }
        uint32_t stb = sb + s * G2_STAGE_B;

#pragma unroll
        for (int ks = 0; ks < 2; ks++) {
            uint32_t koff = (uint32_t)(ks * 16 * 2);
            uint32_t a[2][4];
#pragma unroll
            for (int mt = 0; mt < 2; mt++)
                ldsm4(a[mt], stb + a_off + mt * 16 * TS2 * 2 + koff);
            uint32_t b[8][2];
#pragma unroll
            for (int np = 0; np < 4; np++) {
                uint32_t r[4];
                ldsm4(r, stb + T2B + b_off + np * 16 * TS2 * 2 + koff);
                b[2 * np][0] = r[0]; b[2 * np][1] = r[1];
                b[2 * np + 1][0] = r[2]; b[2 * np + 1][1] = r[3];
            }
#pragma unroll
            for (int mt = 0; mt < 2; mt++)
#pragma unroll
                for (int nt = 0; nt < 8; nt++)
                    mma_f16(acc[mt][nt], a[mt], b[nt]);
        }
    }

    float sq = 0.f;
#pragma unroll
    for (int mt = 0; mt < 2; mt++) {
        int r = m0 + wm + mt * 16 + (lane >> 2);
#pragma unroll
        for (int nt = 0; nt < 8; nt++) {
            int c = j0 + wn + nt * 8 + (lane & 3) * 2;
            size_t o0 = (size_t)r * D + c;
            size_t o1 = (size_t)(r + 8) * D + c;
            float2 u0, u1;
            u0.x = acc[mt][nt][0]; u0.y = acc[mt][nt][1];
            u1.x = acc[mt][nt][2]; u1.y = acc[mt][nt][3];
            *(float2*)(out + o0) = u0;
            *(float2*)(out + o1) = u1;
            float d;
            d = Z[o0] - u0.x;     sq = fmaf(d, d, sq);
            d = Z[o0 + 1] - u0.y; sq = fmaf(d, d, sq);
            d = Z[o1] - u1.x;     sq = fmaf(d, d, sq);
            d = Z[o1 + 1] - u1.y; sq = fmaf(d, d, sq);
        }
    }
    for (int o = 16; o; o >>= 1) sq += __shfl_xor_sync(~0u, sq, o);
    __shared__ float ssq[8];
    if ((tid & 31) == 0) ssq[tid >> 5] = sq;
    __syncthreads();
    if (tid == 0) {
        float t = 0.f;
#pragma unroll
        for (int i = 0; i < 8; i++) t += ssq[i];
        g_sq_partial[blockIdx.y * gridDim.x + blockIdx.x] = (double)t;
    }
}

// ---------------- finalize: loss + perplexity ----------------
__global__ __launch_bounds__(256) void finalize_kernel(const float* __restrict__ varq,
                                                       float* __restrict__ out) {
    int tid = threadIdx.x;
    double ent = 0.0, kld = 0.0, sq = 0.0;
    for (int k = tid; k < KCB; k += 256) {
        float a = 0.f;
#pragma unroll
        for (int c = 0; c < 32; c++) a += g_avg_partial[c][k];
        a *= (1.0f / (float)NROWS);
        ent += (double)(a * logf(a + 1e-7f));
    }
    for (int r = tid; r < NROWS; r += 256) kld += (double)g_rowkld[r];
    if (tid < 128) sq = g_sq_partial[tid];
    __shared__ double red[3][256];
    red[0][tid] = ent; red[1][tid] = kld; red[2][tid] = sq;
    __syncthreads();
    for (int o = 128; o; o >>= 1) {
        if (tid < o) {
            red[0][tid] += red[0][tid + o];
            red[1][tid] += red[1][tid + o];
            red[2][tid] += red[2][tid + o];
        }
        __syncthreads();
    }
    if (tid == 0) {
        float w = 0.5f / fmaxf(varq[0], 1e-10f);
        double loss = red[1][0] / 8.0 + (double)w * red[2][0] / 8.0;
        out[(size_t)NROWS * D]     = (float)loss;
        out[(size_t)NROWS * D + 1] = expf(-(float)red[0][0]);
    }
}

// ---------------- launch ----------------
extern "C" void kernel_launch(void* const* d_in, const int* in_sizes, int n_in,
                              void* d_out, int out_size) {
    const float* z    = (const float*)d_in[0];
    const float* varq = (const float*)d_in[1];
    const float* cb   = (const float*)d_in[2];
    float* out = (float*)d_out;

    static cudaStream_t s2 = nullptr;
    static cudaEvent_t evC = nullptr, evD = nullptr;
    static int infra_ok = -1;
    if (infra_ok < 0) {
        infra_ok = 1;
        if (cudaStreamCreateWithFlags(&s2, cudaStreamNonBlocking) != cudaSuccess) infra_ok = 0;
        if (cudaEventCreateWithFlags(&evC, cudaEventDisableTiming) != cudaSuccess) infra_ok = 0;
        if (cudaEventCreateWithFlags(&evD, cudaEventDisableTiming) != cudaSuccess) infra_ok = 0;
    }
    cudaFuncSetAttribute(gemm1_mma, cudaFuncAttributeMaxDynamicSharedMemorySize, G1_SMEM);
    cudaFuncSetAttribute(gemm2_mma, cudaFuncAttributeMaxDynamicSharedMemorySize, G2_SMEM);

    split_kernel<<<KCB + NROWS, 128>>>(z, cb);
    transpose_kernel<<<dim3(KCB / 32, D / 32), 256>>>(cb);
    gemm1_mma<<<dim3(KCB / 128, NROWS / 128), 256, G1_SMEM>>>(varq);
    passC_kernel<<<NROWS, 512>>>();

    if (infra_ok) {
        cudaEventRecord(evC, 0);
        cudaStreamWaitEvent(s2, evC, 0);
        avg_kernel<<<dim3(32, 32), 256, 0, s2>>>();
        cudaEventRecord(evD, s2);

        gemm2_mma<<<dim3(D / 128, NROWS / 128), 256, G2_SMEM>>>(z, out);

        cudaStreamWaitEvent(0, evD, 0);
        finalize_kernel<<<1, 256>>>(varq, out);
    } else {
        avg_kernel<<<dim3(32, 32), 256>>>();
        gemm2_mma<<<dim3(D / 128, NROWS / 128), 256, G2_SMEM>>>(z, out);
        finalize_kernel<<<1, 256>>>(varq, out);
    }
}

// round 17
// speedup vs baseline: 1.2036x; 1.1749x over previous
#include <cuda_runtime.h>
#include <cuda_bf16.h>
#include <cuda_fp16.h>
#include <cstdint>
#include <math.h>

#define NROWS 4096
#define D     512
#define KCB   8192

// ---------------- scratch (device globals; no allocation) ----------------
__device__ float  g_L[(size_t)NROWS * KCB];     // logits
__device__ float  g_G[(size_t)NROWS * KCB];     // 2*gumbel noise (fp32)
__device__ __half g_E1[(size_t)NROWS * KCB];    // encodings (fp16)
__device__ __half g_A1[(size_t)NROWS * D];      // z fp16 2-way split
__device__ __half g_A2[(size_t)NROWS * D];
__device__ __half g_B1[(size_t)KCB * D];        // cb fp16 2-way split
__device__ __half g_B2[(size_t)KCB * D];
__device__ __half g_CT[(size_t)D * KCB];        // codebook^T (fp16)
__device__ float  g_c2[KCB];
__device__ float  g_z2[NROWS];
__device__ float  g_lse_p[NROWS];
__device__ float  g_lse_e[NROWS];
__device__ float  g_rowkld[NROWS];
__device__ float  g_avg_partial[32][KCB];
__device__ double g_sq_partial[128];

// ---------------- helpers ----------------
__device__ __forceinline__ uint32_t smem_u32(const void* p) {
    uint32_t a;
    asm("{ .reg .u64 t; cvta.to.shared.u64 t, %1; cvt.u32.u64 %0, t; }"
        : "=r"(a) : "l"(p));
    return a;
}
__device__ __forceinline__ void ldsm4(uint32_t* r, uint32_t a) {
    asm volatile("ldmatrix.sync.aligned.m8n8.x4.shared.b16 {%0,%1,%2,%3}, [%4];"
                 : "=r"(r[0]), "=r"(r[1]), "=r"(r[2]), "=r"(r[3]) : "r"(a));
}
__device__ __forceinline__ void mma_f16(float* d, const uint32_t* a, const uint32_t* b) {
    asm volatile("mma.sync.aligned.m16n8k16.row.col.f32.f16.f16.f32 "
                 "{%0,%1,%2,%3}, {%4,%5,%6,%7}, {%8,%9}, {%0,%1,%2,%3};"
                 : "+f"(d[0]), "+f"(d[1]), "+f"(d[2]), "+f"(d[3])
                 : "r"(a[0]), "r"(a[1]), "r"(a[2]), "r"(a[3]), "r"(b[0]), "r"(b[1]));
}
__device__ __forceinline__ void cp16(uint32_t dst, const void* src) {
    asm volatile("cp.async.cg.shared.global [%0], [%1], 16;" :: "r"(dst), "l"(src));
}
#define CP_COMMIT() asm volatile("cp.async.commit_group;")
#define CP_WAIT0()  asm volatile("cp.async.wait_group 0;")

// ---------------- threefry2x32, key = (0, 42), partitionable ----------------
__device__ __forceinline__ void threefry42(uint32_t x0, uint32_t x1,
                                           uint32_t& o0, uint32_t& o1) {
    const uint32_t ks0 = 0u, ks1 = 42u, ks2 = 0x1BD11BDAu ^ 0u ^ 42u;
#define TF_RND(r) { x0 += x1; x1 = __funnelshift_l(x1, x1, (r)); x1 ^= x0; }
    x0 += ks0; x1 += ks1;
    TF_RND(13) TF_RND(15) TF_RND(26) TF_RND(6)
    x0 += ks1; x1 += ks2 + 1u;
    TF_RND(17) TF_RND(29) TF_RND(16) TF_RND(24)
    x0 += ks2; x1 += ks0 + 2u;
    TF_RND(13) TF_RND(15) TF_RND(26) TF_RND(6)
    x0 += ks0; x1 += ks1 + 3u;
    TF_RND(17) TF_RND(29) TF_RND(16) TF_RND(24)
    x0 += ks1; x1 += ks2 + 4u;
    TF_RND(13) TF_RND(15) TF_RND(26) TF_RND(6)
    x0 += ks2; x1 += ks0 + 5u;
#undef TF_RND
    o0 = x0; o1 = x1;
}
__device__ __forceinline__ float bits_to_uniform(uint32_t b) {
    float f = __uint_as_float((b >> 9) | 0x3f800000u) - 1.0f;
    return fmaxf(0.0f, f);
}
__device__ __forceinline__ float gumbel2_from_idx(uint32_t idx) {
    uint32_t o0, o1;
    threefry42(0u, idx, o0, o1);
    float u = bits_to_uniform(o0 ^ o1);
    return -2.f * __logf(-__logf(u + 1e-10f) + 1e-10f);
}
__device__ __forceinline__ void comb(float& m, float& s1, float& s2,
                                     float m2, float s12, float s22) {
    float M = fmaxf(m, m2);
    float a = __expf(m - M), b = __expf(m2 - M);
    s1 = s1 * a + s12 * b;
    s2 = s2 * a + s22 * b;
    m = M;
}

// ---------------- gumbel noise (ALU-bound; main stream) ----------------
__global__ __launch_bounds__(512) void gumbel_kernel() {
    size_t base = (size_t)blockIdx.x * KCB;
    int tid = threadIdx.x;
#pragma unroll 4
    for (int it = 0; it < 16; it++) {
        int k = tid + it * 512;
        g_G[base + k] = gumbel2_from_idx((uint32_t)(base + (size_t)k));
    }
}

// ---------------- split (one-time, fp16 2-way) + norms (mem-bound; side stream) ----------------
__global__ void split_kernel(const float* __restrict__ z, const float* __restrict__ cb) {
    int row = blockIdx.x;
    const float* src;
    __half *d1, *d2;
    float* nrm;
    if (row < KCB) {
        src = cb + (size_t)row * D;
        d1 = g_B1 + (size_t)row * D; d2 = g_B2 + (size_t)row * D;
        nrm = g_c2 + row;
    } else {
        int r = row - KCB;
        src = z + (size_t)r * D;
        d1 = g_A1 + (size_t)r * D; d2 = g_A2 + (size_t)r * D;
        nrm = g_z2 + r;
    }
    float s = 0.f;
    for (int i = threadIdx.x; i < D; i += 128) {
        float v = src[i];
        s = fmaf(v, v, s);
        __half h1 = __float2half_rn(v);
        float r1 = v - __half2float(h1);
        d1[i] = h1; d2[i] = __float2half_rn(r1);
    }
    for (int o = 16; o; o >>= 1) s += __shfl_xor_sync(~0u, s, o);
    __shared__ float sm[4];
    if ((threadIdx.x & 31) == 0) sm[threadIdx.x >> 5] = s;
    __syncthreads();
    if (threadIdx.x == 0) *nrm = sm[0] + sm[1] + sm[2] + sm[3];
}

// ---------------- transpose codebook to fp16: CT[j][k] = cb[k][j] ----------------
__global__ __launch_bounds__(256) void transpose_kernel(const float* __restrict__ cb) {
    __shared__ float t[32][33];
    int k0 = blockIdx.x * 32, j0 = blockIdx.y * 32;
    int tx = threadIdx.x & 31, ty = threadIdx.x >> 5;
#pragma unroll
    for (int i = 0; i < 4; i++)
        t[ty + i * 8][tx] = cb[(size_t)(k0 + ty + i * 8) * D + j0 + tx];
    __syncthreads();
#pragma unroll
    for (int i = 0; i < 4; i++) {
        float v = t[tx][ty + i * 8];
        g_CT[(size_t)(j0 + ty + i * 8) * KCB + k0 + tx] = __float2half_rn(v);
    }
}

// ================ GEMM1 (fp16 HMMA, 3 products, k-chunk 32, 1 sync/iter) ================
#define TS1 40
#define T1B (128 * TS1 * 2)          // 10240 B per tile
#define G1_STAGE_B (4 * T1B)         // 40960
#define G1_SMEM (2 * G1_STAGE_B)     // 81920

__global__ __launch_bounds__(256) void gemm1_mma(const float* __restrict__ varq) {
    extern __shared__ __half smp[];
    uint32_t sb = smem_u32(smp);
    int tid = threadIdx.x, lane = tid & 31, wid = tid >> 5;
    int wm = (wid & 3) * 32, wn = (wid >> 2) * 64;
    int n0 = blockIdx.x * 128, m0 = blockIdx.y * 128;

    float acc[2][8][4];
#pragma unroll
    for (int i = 0; i < 2; i++)
#pragma unroll
        for (int j = 0; j < 8; j++)
#pragma unroll
            for (int q = 0; q < 4; q++) acc[i][j][q] = 0.f;

    int srow = tid >> 1, scol = (tid & 1) * 16;
    size_t aoff = (size_t)(m0 + srow) * D + scol;
    size_t boff = (size_t)(n0 + srow) * D + scol;
    uint32_t st_byte = (uint32_t)(srow * TS1 + scol) * 2;

    uint32_t a_off = (uint32_t)(((wm + (lane & 15)) * TS1 + (lane >> 4) * 8) * 2);
    uint32_t b_off = (uint32_t)(((wn + (lane >> 4) * 8 + (lane & 7)) * TS1 +
                                 ((lane >> 3) & 1) * 8) * 2);

#define G1_CPLOAD(s, kc)                                              \
    {                                                                 \
        uint32_t d0 = sb + (s) * G1_STAGE_B + st_byte;                \
        cp16(d0 + 0 * T1B,      g_A1 + aoff + (kc));                  \
        cp16(d0 + 0 * T1B + 16, g_A1 + aoff + (kc) + 8);              \
        cp16(d0 + 1 * T1B,      g_A2 + aoff + (kc));                  \
        cp16(d0 + 1 * T1B + 16, g_A2 + aoff + (kc) + 8);              \
        cp16(d0 + 2 * T1B,      g_B1 + boff + (kc));                  \
        cp16(d0 + 2 * T1B + 16, g_B1 + boff + (kc) + 8);              \
        cp16(d0 + 3 * T1B,      g_B2 + boff + (kc));                  \
        cp16(d0 + 3 * T1B + 16, g_B2 + boff + (kc) + 8);              \
    }

    G1_CPLOAD(0, 0);
    CP_COMMIT();
    int s = 0;
    for (int kc = 0; kc < D; kc += 32, s ^= 1) {
        CP_WAIT0();
        __syncthreads();
        if (kc + 32 < D) {
            G1_CPLOAD(s ^ 1, kc + 32);
            CP_COMMIT();
        }
        uint32_t stb = sb + s * G1_STAGE_B;

#pragma unroll
        for (int ks = 0; ks < 2; ks++) {
            uint32_t koff = (uint32_t)(ks * 16 * 2);
            uint32_t a[2][2][4];
#pragma unroll
            for (int v = 0; v < 2; v++)
#pragma unroll
                for (int mt = 0; mt < 2; mt++)
                    ldsm4(a[v][mt], stb + v * T1B + a_off + mt * 16 * TS1 * 2 + koff);
            uint32_t b[2][8][2];
#pragma unroll
            for (int v = 0; v < 2; v++)
#pragma unroll
                for (int np = 0; np < 4; np++) {
                    uint32_t r[4];
                    ldsm4(r, stb + (2 + v) * T1B + b_off + np * 16 * TS1 * 2 + koff);
                    b[v][2 * np][0] = r[0]; b[v][2 * np][1] = r[1];
                    b[v][2 * np + 1][0] = r[2]; b[v][2 * np + 1][1] = r[3];
                }
            const int pa[3] = {0, 0, 1};
            const int pb[3] = {0, 1, 0};
#pragma unroll
            for (int p = 0; p < 3; p++)
#pragma unroll
                for (int mt = 0; mt < 2; mt++)
#pragma unroll
                    for (int nt = 0; nt < 8; nt++)
                        mma_f16(acc[mt][nt], a[pa[p]][mt], b[pb[p]][nt]);
        }
    }

    float w = 0.5f / fmaxf(varq[0], 1e-10f);
#pragma unroll
    for (int mt = 0; mt < 2; mt++) {
        int r = m0 + wm + mt * 16 + (lane >> 2);
        float z0 = g_z2[r], z1 = g_z2[r + 8];
#pragma unroll
        for (int nt = 0; nt < 8; nt++) {
            int c = n0 + wn + nt * 8 + (lane & 3) * 2;
            float c20 = g_c2[c], c21 = g_c2[c + 1];
            float2 u0, u1;
            u0.x = 2.f * w * acc[mt][nt][0] - w * (z0 + c20);
            u0.y = 2.f * w * acc[mt][nt][1] - w * (z0 + c21);
            u1.x = 2.f * w * acc[mt][nt][2] - w * (z1 + c20);
            u1.y = 2.f * w * acc[mt][nt][3] - w * (z1 + c21);
            *(float2*)(g_L + (size_t)r * KCB + c) = u0;
            *(float2*)(g_L + (size_t)(r + 8) * KCB + c) = u1;
        }
    }
}

// ---------------- pass C: row softmax stats; reads precomputed gumbel ----------------
__global__ __launch_bounds__(512) void passC_kernel() {
    int n = blockIdx.x;
    size_t base = (size_t)n * KCB;
    int tid = threadIdx.x;

    __shared__ float s_ev[KCB];
    float mp = -3.4e38f, s1 = 0.f, s2 = 0.f;
    float me = -3.4e38f, se = 0.f;

#pragma unroll 4
    for (int it = 0; it < 16; it++) {
        int k = tid + it * 512;
        float l = g_L[base + k];
        float gg = g_G[base + k];
        float e = fmaf(2.f, l, gg);
        s_ev[k] = e;
        if (l <= mp) {
            float b = __expf(l - mp);
            s1 += b; s2 = fmaf(l, b, s2);
        } else {
            float a = __expf(mp - l);
            s1 = fmaf(s1, a, 1.f);
            s2 = fmaf(s2, a, l);
            mp = l;
        }
        if (e <= me) {
            se += __expf(e - me);
        } else {
            se = fmaf(se, __expf(me - e), 1.f);
            me = e;
        }
    }

    for (int o = 16; o; o >>= 1) {
        float m2, a2, b2;
        m2 = __shfl_xor_sync(~0u, mp, o); a2 = __shfl_xor_sync(~0u, s1, o); b2 = __shfl_xor_sync(~0u, s2, o);
        comb(mp, s1, s2, m2, a2, b2);
        float d0 = 0.f;
        m2 = __shfl_xor_sync(~0u, me, o); a2 = __shfl_xor_sync(~0u, se, o); b2 = __shfl_xor_sync(~0u, d0, o);
        comb(me, se, d0, m2, a2, b2);
    }

    __shared__ float sm[16][5];
    __shared__ float s_lse;
    if ((tid & 31) == 0) {
        int w = tid >> 5;
        sm[w][0] = mp; sm[w][1] = s1; sm[w][2] = s2;
        sm[w][3] = me; sm[w][4] = se;
    }
    __syncthreads();
    if (tid == 0) {
        float Mp = sm[0][0], S1 = sm[0][1], S2 = sm[0][2];
        float Me = sm[0][3], Se = sm[0][4];
        for (int w = 1; w < 16; w++) {
            comb(Mp, S1, S2, sm[w][0], sm[w][1], sm[w][2]);
            float d = 0.f;
            comb(Me, Se, d, sm[w][3], sm[w][4], 0.f);
        }
        float lsep = Mp + logf(S1);
        g_lse_p[n]  = lsep;
        g_rowkld[n] = S2 / S1 - lsep;
        float lsee = Me + logf(Se);
        g_lse_e[n]  = lsee;
        s_lse = lsee;
    }
    __syncthreads();
    float lse = s_lse;
#pragma unroll 4
    for (int it = 0; it < 8; it++) {
        int k = tid * 2 + it * 1024;
        float p0 = __expf(s_ev[k] - lse);
        float p1 = __expf(s_ev[k + 1] - lse);
        __half2 h2 = __floats2half2_rn(p0, p1);
        *(__half2*)(g_E1 + base + k) = h2;
    }
}

// ---------------- avg_probs partials (column pass over L) ----------------
__global__ __launch_bounds__(256) void avg_kernel() {
    int k = blockIdx.x * 256 + threadIdx.x;
    int c = blockIdx.y;
    const float* base = g_L + (size_t)c * 128 * KCB + k;
    const float* lse  = g_lse_p + c * 128;
    float s = 0.f;
#pragma unroll 4
    for (int n = 0; n < 128; n++)
        s += __expf(base[(size_t)n * KCB] - lse[n]);
    g_avg_partial[c][k] = s;
}

// ================ GEMM2 (fp16 HMMA, 1 product, k-chunk 32, 1 sync/iter) ================
#define TS2 40
#define T2B (128 * TS2 * 2)          // 10240 B per tile
#define G2_STAGE_B (2 * T2B)         // 20480 (E1, CT)
#define G2_SMEM (2 * G2_STAGE_B)     // 40960

__global__ __launch_bounds__(256) void gemm2_mma(const float* __restrict__ Z,
                                                 float* __restrict__ out) {
    extern __shared__ __half smp2[];
    uint32_t sb = smem_u32(smp2);
    int tid = threadIdx.x, lane = tid & 31, wid = tid >> 5;
    int wm = (wid & 3) * 32, wn = (wid >> 2) * 64;
    int j0 = blockIdx.x * 128, m0 = blockIdx.y * 128;

    float acc[2][8][4];
#pragma unroll
    for (int i = 0; i < 2; i++)
#pragma unroll
        for (int j = 0; j < 8; j++)
#pragma unroll
            for (int q = 0; q < 4; q++) acc[i][j][q] = 0.f;

    int srow = tid >> 1, scol = (tid & 1) * 16;
    size_t aoff = (size_t)(m0 + srow) * KCB + scol;
    size_t boff = (size_t)(j0 + srow) * KCB + scol;
    uint32_t st_byte = (uint32_t)(srow * TS2 + scol) * 2;

    uint32_t a_off = (uint32_t)(((wm + (lane & 15)) * TS2 + (lane >> 4) * 8) * 2);
    uint32_t b_off = (uint32_t)(((wn + (lane >> 4) * 8 + (lane & 7)) * TS2 +
                                 ((lane >> 3) & 1) * 8) * 2);

#define G2_CPLOAD(s, kc)                                              \
    {                                                                 \
        uint32_t d0 = sb + (s) * G2_STAGE_B + st_byte;                \
        cp16(d0 + 0 * T2B,      g_E1 + aoff + (kc));                  \
        cp16(d0 + 0 * T2B + 16, g_E1 + aoff + (kc) + 8);              \
        cp16(d0 + 1 * T2B,      g_CT + boff + (kc));                  \
        cp16(d0 + 1 * T2B + 16, g_CT + boff + (kc) + 8);              \
    }

    G2_CPLOAD(0, 0);
    CP_COMMIT();
    int s = 0;
    for (int kc = 0; kc < KCB; kc += 32, s ^= 1) {
        CP_WAIT0();
        __syncthreads();
        if (kc + 32 < KCB) {
            G2_CPLOAD(s ^ 1, kc + 32);
            CP_COMMIT();
        }
        uint32_t stb = sb + s * G2_STAGE_B;

#pragma unroll
        for (int ks = 0; ks < 2; ks++) {
            uint32_t koff = (uint32_t)(ks * 16 * 2);
            uint32_t a[2][4];
#pragma unroll
            for (int mt = 0; mt < 2; mt++)
                ldsm4(a[mt], stb + a_off + mt * 16 * TS2 * 2 + koff);
            uint32_t b[8][2];
#pragma unroll
            for (int np = 0; np < 4; np++) {
                uint32_t r[4];
                ldsm4(r, stb + T2B + b_off + np * 16 * TS2 * 2 + koff);
                b[2 * np][0] = r[0]; b[2 * np][1] = r[1];
                b[2 * np + 1][0] = r[2]; b[2 * np + 1][1] = r[3];
            }
#pragma unroll
            for (int mt = 0; mt < 2; mt++)
#pragma unroll
                for (int nt = 0; nt < 8; nt++)
                    mma_f16(acc[mt][nt], a[mt], b[nt]);
        }
    }

    float sq = 0.f;
#pragma unroll
    for (int mt = 0; mt < 2; mt++) {
        int r = m0 + wm + mt * 16 + (lane >> 2);
#pragma unroll
        for (int nt = 0; nt < 8; nt++) {
            int c = j0 + wn + nt * 8 + (lane & 3) * 2;
            size_t o0 = (size_t)r * D + c;
            size_t o1 = (size_t)(r + 8) * D + c;
            float2 u0, u1;
            u0.x = acc[mt][nt][0]; u0.y = acc[mt][nt][1];
            u1.x = acc[mt][nt][2]; u1.y = acc[mt][nt][3];
            *(float2*)(out + o0) = u0;
            *(float2*)(out + o1) = u1;
            float d;
            d = Z[o0] - u0.x;     sq = fmaf(d, d, sq);
            d = Z[o0 + 1] - u0.y; sq = fmaf(d, d, sq);
            d = Z[o1] - u1.x;     sq = fmaf(d, d, sq);
            d = Z[o1 + 1] - u1.y; sq = fmaf(d, d, sq);
        }
    }
    for (int o = 16; o; o >>= 1) sq += __shfl_xor_sync(~0u, sq, o);
    __shared__ float ssq[8];
    if ((tid & 31) == 0) ssq[tid >> 5] = sq;
    __syncthreads();
    if (tid == 0) {
        float t = 0.f;
#pragma unroll
        for (int i = 0; i < 8; i++) t += ssq[i];
        g_sq_partial[blockIdx.y * gridDim.x + blockIdx.x] = (double)t;
    }
}

// ---------------- finalize: loss + perplexity ----------------
__global__ __launch_bounds__(256) void finalize_kernel(const float* __restrict__ varq,
                                                       float* __restrict__ out) {
    int tid = threadIdx.x;
    double ent = 0.0, kld = 0.0, sq = 0.0;
    for (int k = tid; k < KCB; k += 256) {
        float a = 0.f;
#pragma unroll
        for (int c = 0; c < 32; c++) a += g_avg_partial[c][k];
        a *= (1.0f / (float)NROWS);
        ent += (double)(a * logf(a + 1e-7f));
    }
    for (int r = tid; r < NROWS; r += 256) kld += (double)g_rowkld[r];
    if (tid < 128) sq = g_sq_partial[tid];
    __shared__ double red[3][256];
    red[0][tid] = ent; red[1][tid] = kld; red[2][tid] = sq;
    __syncthreads();
    for (int o = 128; o; o >>= 1) {
        if (tid < o) {
            red[0][tid] += red[0][tid + o];
            red[1][tid] += red[1][tid + o];
            red[2][tid] += red[2][tid + o];
        }
        __syncthreads();
    }
    if (tid == 0) {
        float w = 0.5f / fmaxf(varq[0], 1e-10f);
        double loss = red[1][0] / 8.0 + (double)w * red[2][0] / 8.0;
        out[(size_t)NROWS * D]     = (float)loss;
        out[(size_t)NROWS * D + 1] = expf(-(float)red[0][0]);
    }
}

// ---------------- launch ----------------
extern "C" void kernel_launch(void* const* d_in, const int* in_sizes, int n_in,
                              void* d_out, int out_size) {
    const float* z    = (const float*)d_in[0];
    const float* varq = (const float*)d_in[1];
    const float* cb   = (const float*)d_in[2];
    float* out = (float*)d_out;

    static cudaStream_t s2 = nullptr;
    static cudaEvent_t evA = nullptr, evB = nullptr, evC = nullptr, evD = nullptr;
    static int infra_ok = -1;
    if (infra_ok < 0) {
        infra_ok = 1;
        if (cudaStreamCreateWithFlags(&s2, cudaStreamNonBlocking) != cudaSuccess) infra_ok = 0;
        if (cudaEventCreateWithFlags(&evA, cudaEventDisableTiming) != cudaSuccess) infra_ok = 0;
        if (cudaEventCreateWithFlags(&evB, cudaEventDisableTiming) != cudaSuccess) infra_ok = 0;
        if (cudaEventCreateWithFlags(&evC, cudaEventDisableTiming) != cudaSuccess) infra_ok = 0;
        if (cudaEventCreateWithFlags(&evD, cudaEventDisableTiming) != cudaSuccess) infra_ok = 0;
    }
    cudaFuncSetAttribute(gemm1_mma, cudaFuncAttributeMaxDynamicSharedMemorySize, G1_SMEM);
    cudaFuncSetAttribute(gemm2_mma, cudaFuncAttributeMaxDynamicSharedMemorySize, G2_SMEM);

    if (infra_ok) {
        // fork: split+transpose (memory-bound) on s2, gumbel (ALU-bound) on main.
        // These co-reside (small register footprints); gemm1 waits for s2.
        cudaEventRecord(evA, 0);
        cudaStreamWaitEvent(s2, evA, 0);
        split_kernel<<<KCB + NROWS, 128, 0, s2>>>(z, cb);
        transpose_kernel<<<dim3(KCB / 32, D / 32), 256, 0, s2>>>(cb);
        cudaEventRecord(evB, s2);

        gumbel_kernel<<<NROWS, 512>>>();

        cudaStreamWaitEvent(0, evB, 0);   // gemm1 needs split outputs
        gemm1_mma<<<dim3(KCB / 128, NROWS / 128), 256, G1_SMEM>>>(varq);
        passC_kernel<<<NROWS, 512>>>();

        // fork: avg on s2 concurrent with gemm2
        cudaEventRecord(evC, 0);
        cudaStreamWaitEvent(s2, evC, 0);
        avg_kernel<<<dim3(32, 32), 256, 0, s2>>>();
        cudaEventRecord(evD, s2);

        gemm2_mma<<<dim3(D / 128, NROWS / 128), 256, G2_SMEM>>>(z, out);

        cudaStreamWaitEvent(0, evD, 0);
        finalize_kernel<<<1, 256>>>(varq, out);
    } else {
        gumbel_kernel<<<NROWS, 512>>>();
        split_kernel<<<KCB + NROWS, 128>>>(z, cb);
        transpose_kernel<<<dim3(KCB / 32, D / 32), 256>>>(cb);
        gemm1_mma<<<dim3(KCB / 128, NROWS / 128), 256, G1_SMEM>>>(varq);
        passC_kernel<<<NROWS, 512>>>();
        avg_kernel<<<dim3(32, 32), 256>>>();
        gemm2_mma<<<dim3(D / 128, NROWS / 128), 256, G2_SMEM>>>(z, out);
        finalize_kernel<<<1, 256>>>(varq, out);
    }
}